// round 5
// baseline (speedup 1.0000x reference)
#include <cuda_runtime.h>
#include <math.h>

// DPLSTMCell row-0: out[n] = LSTM epilogue over 8 dot-products (4 gates x {Wih,Whh}).
// R5 = R4 fixed: sm_103a requires .v8.b32 width for L2::evict_last -> use LDG.256.
//  1. Weights loaded with ld.global.nc.L2::evict_last.v8.b32 -> 32MB weight set stays
//     resident in the 126MB L2 across graph replays; replays 2..N hit L2.
//  2. All 4 (256-bit) weight loads front-batched into registers: 4KB in-flight/warp.
// Vectors x/h (8KB hot) staged via smem.

#define H 1024
#define D 1024

struct f8 { float a0,a1,a2,a3,a4,a5,a6,a7; };

__device__ __forceinline__ float warp_reduce(float v) {
    #pragma unroll
    for (int off = 16; off > 0; off >>= 1)
        v += __shfl_xor_sync(0xFFFFFFFFu, v, off);
    return v;
}

__device__ __forceinline__ f8 ldg256_evict_last(const float* p) {
    f8 r;
    asm volatile("ld.global.nc.L2::evict_last.v8.b32 "
                 "{%0,%1,%2,%3,%4,%5,%6,%7}, [%8];"
                 : "=f"(r.a0), "=f"(r.a1), "=f"(r.a2), "=f"(r.a3),
                   "=f"(r.a4), "=f"(r.a5), "=f"(r.a6), "=f"(r.a7)
                 : "l"(p));
    return r;
}

__global__ __launch_bounds__(256)
void lstm_row0_kernel(const float* __restrict__ x,
                      const float* __restrict__ h,
                      const float* __restrict__ c_prev,
                      const float* __restrict__ Wih,
                      const float* __restrict__ Whh,
                      const float* __restrict__ bih,
                      const float* __restrict__ bhh,
                      float* __restrict__ out) {
    __shared__ float4 sx[D / 4];   // 4KB
    __shared__ float4 sh[H / 4];   // 4KB
    __shared__ float  sums[8];

    const int n    = blockIdx.x;          // output element [0, 1024)
    const int tid  = threadIdx.x;
    const int wid  = tid >> 5;            // 0..7 : which of 8 dot products
    const int lane = tid & 31;

    // warp -> (gate, matrix): gate = wid>>1, mat = wid&1
    const int gate = wid >> 1;
    const int mat  = wid & 1;
    const int row  = gate * H + n;

    const float* __restrict__ W = (mat ? Whh : Wih) + (size_t)row * D;

    // Front-batch ALL weight loads as 4 x LDG.256 per lane (4KB in flight per warp),
    // evict_last keeps the 32MB weight set L2-resident across graph replays.
    f8 w[4];
    #pragma unroll
    for (int i = 0; i < 4; i++)
        w[i] = ldg256_evict_last(W + lane * 8 + i * 256);

    // Stage the two hot 4KB vectors into smem while weight loads are in flight.
    sx[tid] = reinterpret_cast<const float4*>(x)[tid];
    sh[tid] = reinterpret_cast<const float4*>(h)[tid];
    __syncthreads();

    const float4* v4 = mat ? sh : sx;

    float acc = 0.0f;
    #pragma unroll
    for (int i = 0; i < 4; i++) {
        // matching vector elements: floats [lane*8 + i*256, +8) = float4 idx lane*2 + i*64
        const float4 xa = v4[lane * 2 + i * 64];
        const float4 xb = v4[lane * 2 + i * 64 + 1];
        acc += w[i].a0 * xa.x + w[i].a1 * xa.y + w[i].a2 * xa.z + w[i].a3 * xa.w;
        acc += w[i].a4 * xb.x + w[i].a5 * xb.y + w[i].a6 * xb.z + w[i].a7 * xb.w;
    }
    acc = warp_reduce(acc);

    if (lane == 0) sums[wid] = acc;
    __syncthreads();

    if (tid == 0) {
        float gi = sums[0] + sums[1] + bih[n]         + bhh[n];
        float gf = sums[2] + sums[3] + bih[H + n]     + bhh[H + n];
        float gg = sums[4] + sums[5] + bih[2 * H + n] + bhh[2 * H + n];
        float go = sums[6] + sums[7] + bih[3 * H + n] + bhh[3 * H + n];

        float i_t = 1.0f / (1.0f + expf(-gi));
        float f_t = 1.0f / (1.0f + expf(-gf));
        float g_t = tanhf(gg);
        float o_t = 1.0f / (1.0f + expf(-go));

        float c_t = f_t * c_prev[n] + i_t * g_t;
        out[n] = o_t * tanhf(c_t);
    }
}

extern "C" void kernel_launch(void* const* d_in, const int* in_sizes, int n_in,
                              void* d_out, int out_size) {
    const float* x      = (const float*)d_in[0];
    const float* h      = (const float*)d_in[1];
    const float* c_prev = (const float*)d_in[2];
    const float* Wih    = (const float*)d_in[3];
    const float* Whh    = (const float*)d_in[4];
    const float* bih    = (const float*)d_in[5];
    const float* bhh    = (const float*)d_in[6];
    float* out = (float*)d_out;

    lstm_row0_kernel<<<H, 256>>>(x, h, c_prev, Wih, Whh, bih, bhh, out);
}

// round 6
// speedup vs baseline: 1.2122x; 1.2122x over previous
#include <cuda_runtime.h>
#include <math.h>
#include <stdint.h>

// DPLSTMCell row-0: out[n] = LSTM epilogue over 8 dot-products (4 gates x {Wih,Whh}).
// R6: weight stream via cp.async.cg (LDGSTS) -> smem. LDG plateaued at 2.8TB/s because
// the SM-wide outstanding-LDG line cap (~64 lines ~ 8KB) bounds in-flight bytes;
// LDGSTS has no observed depth cap, so per-SM in-flight rises to ~224KB (7 blocks x 32KB)
// and DRAM becomes the limiter. Default cache policy keeps weights L2-warm across replays.

#define H 1024
#define D 1024

__device__ __forceinline__ float warp_reduce(float v) {
    #pragma unroll
    for (int off = 16; off > 0; off >>= 1)
        v += __shfl_xor_sync(0xFFFFFFFFu, v, off);
    return v;
}

__global__ __launch_bounds__(256, 7)
void lstm_row0_cpasync_kernel(const float* __restrict__ x,
                              const float* __restrict__ h,
                              const float* __restrict__ c_prev,
                              const float* __restrict__ Wih,
                              const float* __restrict__ Whh,
                              const float* __restrict__ bih,
                              const float* __restrict__ bhh,
                              float* __restrict__ out) {
    __shared__ __align__(128) float4 swt[8 * 256];  // 8 rows x 4KB = 32KB
    __shared__ float sums[8];

    const int n    = blockIdx.x;
    const int tid  = threadIdx.x;
    const int wid  = tid >> 5;            // 0..7 : (gate,mat) row
    const int lane = tid & 31;

    // Issue 8 cp.async.cg per thread: chunk k = weight row k, thread tid copies float4 #tid.
    #pragma unroll
    for (int k = 0; k < 8; k++) {
        const int gate = k >> 1;
        const int mat  = k & 1;
        const float* src = (mat ? Whh : Wih) + (size_t)(gate * H + n) * D + tid * 4;
        const uint32_t dst =
            (uint32_t)__cvta_generic_to_shared(&swt[k * 256 + tid]);
        asm volatile("cp.async.cg.shared.global [%0], [%1], 16;"
                     :: "r"(dst), "l"(src) : "memory");
    }
    asm volatile("cp.async.commit_group;" ::: "memory");

    // While weights stream, prefetch this warp's vector (hot 4KB, L2-broadcast).
    const int mat = wid & 1;
    const float4* __restrict__ v4 = reinterpret_cast<const float4*>(mat ? h : x);
    float4 xv[8];
    #pragma unroll
    for (int i = 0; i < 8; i++)
        xv[i] = __ldg(&v4[lane + i * 32]);

    asm volatile("cp.async.wait_group 0;" ::: "memory");
    __syncthreads();

    // Dot product: weights from smem (conflict-free LDS.128), vector in regs.
    const float4* w4 = &swt[wid * 256];
    float acc = 0.0f;
    #pragma unroll
    for (int i = 0; i < 8; i++) {
        const float4 wv = w4[lane + i * 32];
        acc += wv.x * xv[i].x + wv.y * xv[i].y + wv.z * xv[i].z + wv.w * xv[i].w;
    }
    acc = warp_reduce(acc);

    if (lane == 0) sums[wid] = acc;
    __syncthreads();

    if (tid == 0) {
        float gi = sums[0] + sums[1] + bih[n]         + bhh[n];
        float gf = sums[2] + sums[3] + bih[H + n]     + bhh[H + n];
        float gg = sums[4] + sums[5] + bih[2 * H + n] + bhh[2 * H + n];
        float go = sums[6] + sums[7] + bih[3 * H + n] + bhh[3 * H + n];

        float i_t = 1.0f / (1.0f + expf(-gi));
        float f_t = 1.0f / (1.0f + expf(-gf));
        float g_t = tanhf(gg);
        float o_t = 1.0f / (1.0f + expf(-go));

        float c_t = f_t * c_prev[n] + i_t * g_t;
        out[n] = o_t * tanhf(c_t);
    }
}

extern "C" void kernel_launch(void* const* d_in, const int* in_sizes, int n_in,
                              void* d_out, int out_size) {
    const float* x      = (const float*)d_in[0];
    const float* h      = (const float*)d_in[1];
    const float* c_prev = (const float*)d_in[2];
    const float* Wih    = (const float*)d_in[3];
    const float* Whh    = (const float*)d_in[4];
    const float* bih    = (const float*)d_in[5];
    const float* bhh    = (const float*)d_in[6];
    float* out = (float*)d_out;

    lstm_row0_cpasync_kernel<<<H, 256>>>(x, h, c_prev, Wih, Whh, bih, bhh, out);
}

// round 7
// speedup vs baseline: 1.2157x; 1.0029x over previous
#include <cuda_runtime.h>
#include <math.h>

// DPLSTMCell row-0: out[n] = LSTM epilogue over 8 dot-products (4 gates x {Wih,Whh}).
// R7 = R1 skeleton (best warm: 8.93us) with:
//  1. LDG.256 weight loads (ld.global.nc.v8.b32): 4 requests/warp instead of 8,
//     all front-batched -> fewer transactions through the L1tex wavefront queue.
//  2. Vector float4 loads issued after the weight burst (L1-hot broadcast).
//  3. Fast epilogue: sigmoid/tanh via tanh.approx.f32 (MUFU), err ~5e-4 << 1e-3 budget.
// No cache hints (evict_last regressed warm replays in R5), no smem staging (R2 worse),
// no cp.async/TMA (R3/R6 worse).

#define H 1024
#define D 1024

struct f8 { float a0,a1,a2,a3,a4,a5,a6,a7; };

__device__ __forceinline__ float warp_reduce(float v) {
    #pragma unroll
    for (int off = 16; off > 0; off >>= 1)
        v += __shfl_xor_sync(0xFFFFFFFFu, v, off);
    return v;
}

__device__ __forceinline__ f8 ldg256(const float* p) {
    f8 r;
    asm volatile("ld.global.nc.v8.b32 {%0,%1,%2,%3,%4,%5,%6,%7}, [%8];"
                 : "=f"(r.a0), "=f"(r.a1), "=f"(r.a2), "=f"(r.a3),
                   "=f"(r.a4), "=f"(r.a5), "=f"(r.a6), "=f"(r.a7)
                 : "l"(p));
    return r;
}

__device__ __forceinline__ float fast_tanh(float x) {
    float r;
    asm("tanh.approx.f32 %0, %1;" : "=f"(r) : "f"(x));
    return r;
}
__device__ __forceinline__ float fast_sigmoid(float x) {
    return 0.5f * fast_tanh(0.5f * x) + 0.5f;
}

__global__ __launch_bounds__(256)
void lstm_row0_kernel(const float* __restrict__ x,
                      const float* __restrict__ h,
                      const float* __restrict__ c_prev,
                      const float* __restrict__ Wih,
                      const float* __restrict__ Whh,
                      const float* __restrict__ bih,
                      const float* __restrict__ bhh,
                      float* __restrict__ out) {
    __shared__ float sums[8];

    const int n    = blockIdx.x;          // output element [0, 1024)
    const int tid  = threadIdx.x;
    const int wid  = tid >> 5;            // 0..7 : which of 8 dot products
    const int lane = tid & 31;

    // warp -> (gate, matrix): gate = wid>>1, mat = wid&1
    const int gate = wid >> 1;
    const int mat  = wid & 1;
    const int row  = gate * H + n;

    const float* __restrict__ W   = (mat ? Whh : Wih) + (size_t)row * D;
    const float* __restrict__ vec = mat ? h : x;

    // Front-batch ALL weight bytes as 4 x LDG.256 per lane (4KB in flight per warp).
    f8 w[4];
    #pragma unroll
    for (int i = 0; i < 4; i++)
        w[i] = ldg256(W + lane * 8 + i * 256);

    // Vector loads (same 8KB for all blocks: L1/L2-hot broadcast).
    const float4* __restrict__ v4 = reinterpret_cast<const float4*>(vec);
    float acc = 0.0f;
    #pragma unroll
    for (int i = 0; i < 4; i++) {
        const float4 xa = __ldg(&v4[lane * 2 + i * 64]);
        const float4 xb = __ldg(&v4[lane * 2 + i * 64 + 1]);
        acc += w[i].a0 * xa.x + w[i].a1 * xa.y + w[i].a2 * xa.z + w[i].a3 * xa.w;
        acc += w[i].a4 * xb.x + w[i].a5 * xb.y + w[i].a6 * xb.z + w[i].a7 * xb.w;
    }
    acc = warp_reduce(acc);

    if (lane == 0) sums[wid] = acc;
    __syncthreads();

    if (tid == 0) {
        float gi = sums[0] + sums[1] + bih[n]         + bhh[n];
        float gf = sums[2] + sums[3] + bih[H + n]     + bhh[H + n];
        float gg = sums[4] + sums[5] + bih[2 * H + n] + bhh[2 * H + n];
        float go = sums[6] + sums[7] + bih[3 * H + n] + bhh[3 * H + n];

        float i_t = fast_sigmoid(gi);
        float f_t = fast_sigmoid(gf);
        float g_t = fast_tanh(gg);
        float o_t = fast_sigmoid(go);

        float c_t = f_t * c_prev[n] + i_t * g_t;
        out[n] = o_t * fast_tanh(c_t);
    }
}

extern "C" void kernel_launch(void* const* d_in, const int* in_sizes, int n_in,
                              void* d_out, int out_size) {
    const float* x      = (const float*)d_in[0];
    const float* h      = (const float*)d_in[1];
    const float* c_prev = (const float*)d_in[2];
    const float* Wih    = (const float*)d_in[3];
    const float* Whh    = (const float*)d_in[4];
    const float* bih    = (const float*)d_in[5];
    const float* bhh    = (const float*)d_in[6];
    float* out = (float*)d_out;

    lstm_row0_kernel<<<H, 256>>>(x, h, c_prev, Wih, Whh, bih, bhh, out);
}

// round 8
// speedup vs baseline: 1.3808x; 1.1358x over previous
#include <cuda_runtime.h>
#include <math.h>
#include <stdint.h>

// DPLSTMCell row-0, R8: software-pipelined persistent blocks.
// grid=296 (2 blocks/SM), 256 threads; each block processes n = bid + 296*it, it=0..3.
// Double-buffered cp.async (2 x 32KB smem): loads for it+2 overlap compute of it.
// Vectors x/h live in registers (loaded once per warp). MUFU fast epilogue (R7-proven).

#define H 1024
#define D 1024
#define NBLK 296
#define NIT 4

__device__ __forceinline__ float warp_reduce(float v) {
    #pragma unroll
    for (int off = 16; off > 0; off >>= 1)
        v += __shfl_xor_sync(0xFFFFFFFFu, v, off);
    return v;
}

__device__ __forceinline__ float fast_tanh(float x) {
    float r;
    asm("tanh.approx.f32 %0, %1;" : "=f"(r) : "f"(x));
    return r;
}
__device__ __forceinline__ float fast_sigmoid(float x) {
    return 0.5f * fast_tanh(0.5f * x) + 0.5f;
}

__global__ __launch_bounds__(256)
void lstm_row0_pipe_kernel(const float* __restrict__ x,
                           const float* __restrict__ h,
                           const float* __restrict__ c_prev,
                           const float* __restrict__ Wih,
                           const float* __restrict__ Whh,
                           const float* __restrict__ bih,
                           const float* __restrict__ bhh,
                           float* __restrict__ out) {
    extern __shared__ float4 buf[];          // [2][8 rows][256 float4] = 2 x 32KB
    __shared__ float sums[2][8];

    const int bid  = blockIdx.x;
    const int tid  = threadIdx.x;
    const int wid  = tid >> 5;               // row 0..7: gate = wid>>1, mat = wid&1
    const int lane = tid & 31;
    const int mat  = wid & 1;
    const int gate = wid >> 1;

    // Preload this warp's vector (x or h) into registers: 8 float4/lane, reused 4x.
    const float4* __restrict__ v4 = reinterpret_cast<const float4*>(mat ? h : x);
    float4 vr[8];
    #pragma unroll
    for (int i = 0; i < 8; i++)
        vr[i] = v4[lane + i * 32];

    // Issue weight loads for iteration 'it' into buf[it&1].
    auto issue = [&](int it) {
        const int n = bid + NBLK * it;
        if (it < NIT && n < H) {
            float4* dst4 = &buf[(it & 1) * 2048];
            #pragma unroll
            for (int r = 0; r < 8; r++) {
                const int g = r >> 1;
                const int m = r & 1;
                const float* src = (m ? Whh : Wih) + (size_t)(g * H + n) * D + tid * 4;
                const uint32_t dst =
                    (uint32_t)__cvta_generic_to_shared(&dst4[r * 256 + tid]);
                asm volatile("cp.async.cg.shared.global [%0], [%1], 16;"
                             :: "r"(dst), "l"(src) : "memory");
            }
        }
        asm volatile("cp.async.commit_group;" ::: "memory");  // always: keep counts uniform
    };

    issue(0);
    issue(1);

    #pragma unroll
    for (int it = 0; it < NIT; it++) {
        const int n = bid + NBLK * it;
        const int b = it & 1;

        asm volatile("cp.async.wait_group 1;" ::: "memory");
        __syncthreads();

        if (n < H) {
            const float4* w4 = &buf[b * 2048 + wid * 256];
            float acc = 0.0f;
            #pragma unroll
            for (int i = 0; i < 8; i++) {
                const float4 wv = w4[lane + i * 32];
                acc += wv.x * vr[i].x + wv.y * vr[i].y
                     + wv.z * vr[i].z + wv.w * vr[i].w;
            }
            acc = warp_reduce(acc);
            if (lane == 0) sums[b][wid] = acc;
        }
        __syncthreads();   // all reads of buf[b] done; sums[b] visible

        if (tid == 0 && n < H) {
            float gi = sums[b][0] + sums[b][1] + bih[n]         + bhh[n];
            float gf = sums[b][2] + sums[b][3] + bih[H + n]     + bhh[H + n];
            float gg = sums[b][4] + sums[b][5] + bih[2 * H + n] + bhh[2 * H + n];
            float go = sums[b][6] + sums[b][7] + bih[3 * H + n] + bhh[3 * H + n];

            float i_t = fast_sigmoid(gi);
            float f_t = fast_sigmoid(gf);
            float g_t = fast_tanh(gg);
            float o_t = fast_sigmoid(go);

            float c_t = f_t * c_prev[n] + i_t * g_t;
            out[n] = o_t * fast_tanh(c_t);
        }

        issue(it + 2);     // refill buf[b]; safe: all reads completed at the bar above
    }
}

extern "C" void kernel_launch(void* const* d_in, const int* in_sizes, int n_in,
                              void* d_out, int out_size) {
    const float* x      = (const float*)d_in[0];
    const float* h      = (const float*)d_in[1];
    const float* c_prev = (const float*)d_in[2];
    const float* Wih    = (const float*)d_in[3];
    const float* Whh    = (const float*)d_in[4];
    const float* bih    = (const float*)d_in[5];
    const float* bhh    = (const float*)d_in[6];
    float* out = (float*)d_out;

    static int smem_set = 0;
    if (!smem_set) {
        cudaFuncSetAttribute(lstm_row0_pipe_kernel,
                             cudaFuncAttributeMaxDynamicSharedMemorySize,
                             2 * 32 * 1024);
        smem_set = 1;
    }
    lstm_row0_pipe_kernel<<<NBLK, 256, 2 * 32 * 1024>>>(
        x, h, c_prev, Wih, Whh, bih, bhh, out);
}